// round 4
// baseline (speedup 1.0000x reference)
#include <cuda_runtime.h>
#include <cstdint>

#define BATCH 8
#define NROI 2000
#define NCLS 81
#define MAXDET 100
#define META_W (12 + NCLS)
#define CAP 128                      // per-class capacity (pow2)
#define K2_THREADS 1024
#define ROIS_PER_BLK 8

typedef unsigned long long u64;
#define KMAX 0xFFFFFFFFFFFFFFFFull
#define SENT43 ((1ull << 43) - 1)    // masked-key sentinel (> any real masked key)
#define SUPBIT (1ull << 63)

// ---------------- device scratch -------------------------------------------
__device__ float4 g_box[BATCH][NROI];
__device__ u64    g_key[BATCH][NROI];

__device__ __forceinline__ unsigned int f2ord(float s) {
    unsigned int u = __float_as_uint(s);
    return (u & 0x80000000u) ? ~u : (u | 0x80000000u);
}
__device__ __forceinline__ float ord2f(unsigned int o) {
    unsigned int u = (o & 0x80000000u) ? (o ^ 0x80000000u) : ~o;
    return __uint_as_float(u);
}

// ============================= Kernel 1 ======================================
// One warp per ROI: argmax over 81 classes, refine, clip; key = cls|score|idx.
__global__ __launch_bounds__(ROIS_PER_BLK * 32)
void refine_kernel(const float* __restrict__ rois,
                   const float* __restrict__ probs,
                   const float* __restrict__ deltas,
                   const float* __restrict__ meta) {
    const int blk  = blockIdx.x;
    const int b    = blk / (NROI / ROIS_PER_BLK);
    const int rblk = blk % (NROI / ROIS_PER_BLK);
    const int warp = threadIdx.x >> 5;
    const int lane = threadIdx.x & 31;
    const int r    = rblk * ROIS_PER_BLK + warp;

    const float* p = probs + ((size_t)b * NROI + r) * NCLS;
    float v = p[lane];
    int ci = lane;
    {
        float v2 = p[lane + 32];
        if (v2 > v) { v = v2; ci = lane + 32; }
        if (lane + 64 < NCLS) {
            float v3 = p[lane + 64];
            if (v3 > v) { v = v3; ci = lane + 64; }
        }
    }
#pragma unroll
    for (int off = 16; off; off >>= 1) {
        float ov = __shfl_down_sync(0xffffffffu, v, off);
        int   oi = __shfl_down_sync(0xffffffffu, ci, off);
        if (ov > v || (ov == v && oi < ci)) { v = ov; ci = oi; }
    }
    if (lane == 0) {
        float h = meta[4], w = meta[5];
        float sy = h - 1.0f, sx = w - 1.0f;
        const float* mw = meta + (size_t)b * META_W + 7;
        float wy1 = mw[0] / sy;
        float wx1 = mw[1] / sx;
        float wy2 = (mw[2] - 1.0f) / sy;
        float wx2 = (mw[3] - 1.0f) / sx;

        float4 roi = *reinterpret_cast<const float4*>(rois + ((size_t)b * NROI + r) * 4);
        float4 d   = *reinterpret_cast<const float4*>(deltas + (((size_t)b * NROI + r) * NCLS + ci) * 4);
        d.x *= 0.1f; d.y *= 0.1f; d.z *= 0.2f; d.w *= 0.2f;
        float hh = roi.z - roi.x;
        float ww = roi.w - roi.y;
        float cy = roi.x + 0.5f * hh + d.x * hh;
        float cx = roi.y + 0.5f * ww + d.y * ww;
        hh *= expf(d.z);
        ww *= expf(d.w);
        float y1 = cy - 0.5f * hh;
        float x1 = cx - 0.5f * ww;
        float y2 = y1 + hh;
        float x2 = x1 + ww;
        y1 = fminf(fmaxf(y1, wy1), wy2);
        x1 = fminf(fmaxf(x1, wx1), wx2);
        y2 = fminf(fmaxf(y2, wy1), wy2);
        x2 = fminf(fmaxf(x2, wx1), wx2);

        g_box[b][r] = make_float4(y1, x1, y2, x2);
        bool valid = (ci > 0) && (v >= 0.7f);
        u64 k = KMAX;
        if (valid) {
            unsigned int desc = ~f2ord(v);
            k = ((u64)ci << 43) | (((u64)desc) << 11) | (unsigned int)r;
        }
        g_key[b][r] = k;
    }
}

// ============================= Kernel 2 ======================================
struct Sm2 {
    u64    lists[NCLS - 1][CAP];   // per-class (score desc, idx asc) keys (masked)
    float4 sbox[NROI];             // boxes by original index
    u64    sel[MAXDET];            // merged top-100: (cls<<43)|maskedkey, ~0 = none
    int    cnt[NCLS];              // per-class counts (index by class 1..80)
};

__global__ __launch_bounds__(K2_THREADS, 1)
void nms_kernel(float* __restrict__ out) {
    extern __shared__ unsigned char smraw[];
    Sm2& sm = *reinterpret_cast<Sm2*>(smraw);

    const int b = blockIdx.x;
    const int tid = threadIdx.x;
    const int lane = tid & 31;
    const int warp = tid >> 5;
    const unsigned lmask = (1u << lane) - 1u;

    if (tid < NCLS) sm.cnt[tid] = 0;
    __syncthreads();

    // ---- coalesced box copy + class bucketing ----
    for (int t = tid; t < NROI; t += K2_THREADS) {
        sm.sbox[t] = g_box[b][t];
        u64 k = g_key[b][t];
        if (k != KMAX) {
            int c = (int)(k >> 43);
            int pos = atomicAdd(&sm.cnt[c], 1);
            if (pos < CAP) sm.lists[c - 1][pos] = k & SENT43;
        }
    }
    __syncthreads();

    // ---- per class (one warp per class): sort, NMS, compact ----
    for (int c = 1 + warp; c <= NCLS - 1; c += K2_THREADS / 32) {
        u64* row = sm.lists[c - 1];
        int n = sm.cnt[c];
        if (n > CAP) n = CAP;

        if (n > 1) {
            // pad to pow2
            int P = 2;
            while (P < n) P <<= 1;
            for (int t = n + lane; t < P; t += 32) row[t] = SENT43;
            __syncwarp();
            // warp bitonic sort (ascending key = score desc, idx asc)
            for (int k2 = 2; k2 <= P; k2 <<= 1) {
                for (int j = k2 >> 1; j > 0; j >>= 1) {
                    for (int i0 = 0; i0 < P; i0 += 32) {
                        int i = i0 + lane;
                        int ixj = i ^ j;
                        if (i < P && ixj > i && ixj < P) {
                            u64 a = row[i];
                            u64 bb = row[ixj];
                            bool up = ((i & k2) == 0);
                            if ((a > bb) == up) { row[i] = bb; row[ixj] = a; }
                        }
                    }
                    __syncwarp();
                }
            }
            // greedy NMS
            for (int i = 0; i < n; ++i) {
                u64 ki = row[i];
                if (ki & SUPBIT) continue;
                int idxi = (int)(ki & 0x7FFu);
                float4 bi = sm.sbox[idxi];
                float areai = (bi.z - bi.x) * (bi.w - bi.y);
                for (int j = i + 1 + lane; j < n; j += 32) {
                    u64 kj = row[j];
                    if (kj & SUPBIT) continue;
                    int idxj = (int)(kj & 0x7FFu);
                    float4 bj = sm.sbox[idxj];
                    float ih = fmaxf(fminf(bi.z, bj.z) - fmaxf(bi.x, bj.x), 0.0f);
                    float iw = fmaxf(fminf(bi.w, bj.w) - fmaxf(bi.y, bj.y), 0.0f);
                    float inter = ih * iw;
                    float areaj = (bj.z - bj.x) * (bj.w - bj.y);
                    float uni = areai + areaj - inter;
                    if (inter / (uni + 1e-8f) > 0.3f) row[j] = kj | SUPBIT;
                }
                __syncwarp();
            }
            // compact kept (preserve order)
            int kn = 0;
            for (int t0 = 0; t0 < n; t0 += 32) {
                int t = t0 + lane;
                u64 k = (t < n) ? row[t] : SUPBIT;
                bool live = (t < n) && !(k & SUPBIT);
                unsigned mball = __ballot_sync(0xffffffffu, live);
                __syncwarp();
                if (live) row[kn + __popc(mball & lmask)] = k;
                kn += __popc(mball);
                __syncwarp();
            }
            if (lane == 0) sm.cnt[c] = kn;
        }
        // n <= 1: list already sorted, nothing suppressed, cnt stays.
    }
    __syncthreads();

    // ---- single-warp 80-way merge: exact top-100 by (score desc, idx asc) ----
    if (warp == 0) {
        // lane owns classes: c0=lane+1 (1..32), c1=lane+33 (33..64), c2=lane+65 (65..80)
        int c0 = lane + 1, c1 = lane + 33, c2 = lane + 65;
        int n0 = sm.cnt[c0];
        int n1 = sm.cnt[c1];
        int n2 = (c2 <= NCLS - 1) ? sm.cnt[c2] : 0;
        int h0 = 0, h1 = 0, h2 = 0;
        u64 cur0 = (h0 < n0) ? sm.lists[c0 - 1][0] : SENT43;
        u64 cur1 = (h1 < n1) ? sm.lists[c1 - 1][0] : SENT43;
        u64 cur2 = (h2 < n2) ? sm.lists[c2 - 1][0] : SENT43;

        for (int step = 0; step < MAXDET; ++step) {
            u64 k = cur0;
            int which = 0;
            if (cur1 < k) { k = cur1; which = 1; }
            if (cur2 < k) { k = cur2; which = 2; }
            u64 p = (k << 7) | ((unsigned)lane << 2) | (unsigned)which;
#pragma unroll
            for (int off = 16; off; off >>= 1) {
                u64 o = __shfl_xor_sync(0xffffffffu, p, off);
                if (o < p) p = o;
            }
            u64 kmin = p >> 7;
            if (kmin >= SENT43) {
                if (lane == 0) sm.sel[step] = KMAX;
            } else {
                int wl = (int)((p >> 2) & 31u);
                int ww = (int)(p & 3u);
                if (lane == wl) {
                    if (ww == 0) { ++h0; cur0 = (h0 < n0) ? sm.lists[c0 - 1][h0] : SENT43; }
                    else if (ww == 1) { ++h1; cur1 = (h1 < n1) ? sm.lists[c1 - 1][h1] : SENT43; }
                    else { ++h2; cur2 = (h2 < n2) ? sm.lists[c2 - 1][h2] : SENT43; }
                }
                if (lane == 0) {
                    int cls = ww * 32 + wl + 1;
                    sm.sel[step] = ((u64)cls << 43) | kmin;
                }
            }
            __syncwarp();
        }
    }
    __syncthreads();

    // ---- emit 100 x 6 ----
    float* ob = out + (size_t)b * MAXDET * 6;
    for (int t = tid; t < MAXDET * 6; t += K2_THREADS) {
        int row = t / 6;
        int col = t - row * 6;
        u64 sv = sm.sel[row];
        float val = 0.0f;
        if (sv != KMAX) {
            int idx = (int)(sv & 0x7FFu);
            if (col < 4) {
                float4 bx = sm.sbox[idx];
                val = (col == 0) ? bx.x : (col == 1) ? bx.y : (col == 2) ? bx.z : bx.w;
            } else if (col == 4) {
                val = (float)((int)(sv >> 43));
            } else {
                unsigned int desc = (unsigned int)((sv >> 11) & 0xFFFFFFFFull);
                val = ord2f(~desc);
            }
        }
        ob[t] = val;
    }
}

extern "C" void kernel_launch(void* const* d_in, const int* in_sizes, int n_in,
                              void* d_out, int out_size) {
    const float* rois   = (const float*)d_in[0];
    const float* probs  = (const float*)d_in[1];
    const float* deltas = (const float*)d_in[2];
    const float* meta   = (const float*)d_in[3];
    float* out = (float*)d_out;

    refine_kernel<<<BATCH * (NROI / ROIS_PER_BLK), ROIS_PER_BLK * 32>>>(rois, probs, deltas, meta);

    size_t smem = sizeof(Sm2);
    cudaFuncSetAttribute(nms_kernel,
                         cudaFuncAttributeMaxDynamicSharedMemorySize, (int)smem);
    nms_kernel<<<BATCH, K2_THREADS, smem>>>(out);
}

// round 5
// speedup vs baseline: 1.2077x; 1.2077x over previous
#include <cuda_runtime.h>
#include <cstdint>

#define BATCH 8
#define NROI 2000
#define NCLS 81
#define NCLS1 (NCLS - 1)
#define MAXDET 100
#define META_W (12 + NCLS)
#define CAP 128
#define ARR 4096
#define ROIS_PER_BLK 8

typedef unsigned long long u64;
#define KMAX 0xFFFFFFFFFFFFFFFFull
#define SENT43 ((1ull << 43) - 1)
#define SUPBIT (1ull << 63)

// ---------------- device scratch -------------------------------------------
__device__ float4 g_box[BATCH][NROI];
__device__ u64    g_key[BATCH][NROI];
__device__ u64    g_kept[BATCH][NCLS1][CAP];
__device__ int    g_kcnt[BATCH][NCLS1];

__device__ __forceinline__ unsigned int f2ord(float s) {
    unsigned int u = __float_as_uint(s);
    return (u & 0x80000000u) ? ~u : (u | 0x80000000u);
}
__device__ __forceinline__ float ord2f(unsigned int o) {
    unsigned int u = (o & 0x80000000u) ? (o ^ 0x80000000u) : ~o;
    return __uint_as_float(u);
}

// ============================= Kernel 1: refine ==============================
// One warp per ROI: argmax over 81 classes, refine, clip; key = cls|score|idx.
__global__ __launch_bounds__(ROIS_PER_BLK * 32)
void refine_kernel(const float* __restrict__ rois,
                   const float* __restrict__ probs,
                   const float* __restrict__ deltas,
                   const float* __restrict__ meta) {
    const int blk  = blockIdx.x;
    const int b    = blk / (NROI / ROIS_PER_BLK);
    const int rblk = blk % (NROI / ROIS_PER_BLK);
    const int warp = threadIdx.x >> 5;
    const int lane = threadIdx.x & 31;
    const int r    = rblk * ROIS_PER_BLK + warp;

    const float* p = probs + ((size_t)b * NROI + r) * NCLS;
    float v = p[lane];
    int ci = lane;
    {
        float v2 = p[lane + 32];
        if (v2 > v) { v = v2; ci = lane + 32; }
        if (lane + 64 < NCLS) {
            float v3 = p[lane + 64];
            if (v3 > v) { v = v3; ci = lane + 64; }
        }
    }
#pragma unroll
    for (int off = 16; off; off >>= 1) {
        float ov = __shfl_down_sync(0xffffffffu, v, off);
        int   oi = __shfl_down_sync(0xffffffffu, ci, off);
        if (ov > v || (ov == v && oi < ci)) { v = ov; ci = oi; }
    }
    if (lane == 0) {
        float h = meta[4], w = meta[5];
        float sy = h - 1.0f, sx = w - 1.0f;
        const float* mw = meta + (size_t)b * META_W + 7;
        float wy1 = mw[0] / sy;
        float wx1 = mw[1] / sx;
        float wy2 = (mw[2] - 1.0f) / sy;
        float wx2 = (mw[3] - 1.0f) / sx;

        float4 roi = *reinterpret_cast<const float4*>(rois + ((size_t)b * NROI + r) * 4);
        float4 d   = *reinterpret_cast<const float4*>(deltas + (((size_t)b * NROI + r) * NCLS + ci) * 4);
        d.x *= 0.1f; d.y *= 0.1f; d.z *= 0.2f; d.w *= 0.2f;
        float hh = roi.z - roi.x;
        float ww = roi.w - roi.y;
        float cy = roi.x + 0.5f * hh + d.x * hh;
        float cx = roi.y + 0.5f * ww + d.y * ww;
        hh *= expf(d.z);
        ww *= expf(d.w);
        float y1 = cy - 0.5f * hh;
        float x1 = cx - 0.5f * ww;
        float y2 = y1 + hh;
        float x2 = x1 + ww;
        y1 = fminf(fmaxf(y1, wy1), wy2);
        x1 = fminf(fmaxf(x1, wx1), wx2);
        y2 = fminf(fmaxf(y2, wy1), wy2);
        x2 = fminf(fmaxf(x2, wx1), wx2);

        g_box[b][r] = make_float4(y1, x1, y2, x2);
        bool valid = (ci > 0) && (v >= 0.7f);
        u64 k = KMAX;
        if (valid) {
            unsigned int desc = ~f2ord(v);
            k = ((u64)ci << 43) | (((u64)desc) << 11) | (unsigned int)r;
        }
        g_key[b][r] = k;
    }
}

// ============================= Kernel 2: per-class NMS =======================
// One warp per (batch, class): scan keys, sort, NMS, write kept list.
__global__ __launch_bounds__(128)
void class_nms_kernel() {
    __shared__ u64    lists[4][CAP];
    __shared__ float4 sbox[4][CAP];
    const int wib  = threadIdx.x >> 5;
    const int lane = threadIdx.x & 31;
    const int g    = blockIdx.x * 4 + wib;
    const int b    = g / NCLS1;
    const int c    = g % NCLS1 + 1;
    u64* row = lists[wib];
    float4* sb = sbox[wib];
    const unsigned lmask = (1u << lane) - 1u;

    // ---- scan all keys for this class (8-deep MLP) ----
    int n = 0;
    for (int t0 = 0; t0 < NROI; t0 += 256) {
        u64 kk[8];
#pragma unroll
        for (int u = 0; u < 8; ++u) {
            int t = t0 + u * 32 + lane;
            kk[u] = (t < NROI) ? g_key[b][t] : KMAX;
        }
#pragma unroll
        for (int u = 0; u < 8; ++u) {
            bool m = ((int)(kk[u] >> 43) == c);
            unsigned ball = __ballot_sync(0xffffffffu, m);
            if (m) {
                int pos = n + __popc(ball & lmask);
                if (pos < CAP) row[pos] = kk[u] & SENT43;
            }
            n += __popc(ball);
        }
    }
    if (n > CAP) n = CAP;
    __syncwarp();

    if (n > 1) {
        // ---- warp bitonic sort: ascending masked key = (score desc, idx asc)
        int P = 2;
        while (P < n) P <<= 1;
        for (int t = n + lane; t < P; t += 32) row[t] = SENT43;
        __syncwarp();
        for (int k2 = 2; k2 <= P; k2 <<= 1) {
            for (int j = k2 >> 1; j > 0; j >>= 1) {
                for (int i0 = 0; i0 < P; i0 += 32) {
                    int i = i0 + lane;
                    int ixj = i ^ j;
                    if (i < P && ixj > i && ixj < P) {
                        u64 a = row[i];
                        u64 bb = row[ixj];
                        bool up = ((i & k2) == 0);
                        if ((a > bb) == up) { row[i] = bb; row[ixj] = a; }
                    }
                }
                __syncwarp();
            }
        }
        // ---- stage boxes ----
        for (int i = lane; i < n; i += 32)
            sb[i] = g_box[b][(int)(row[i] & 0x7FFu)];
        __syncwarp();
        // ---- greedy NMS ----
        for (int i = 0; i < n; ++i) {
            u64 ki = row[i];
            if (ki & SUPBIT) continue;
            float4 bi = sb[i];
            float areai = (bi.z - bi.x) * (bi.w - bi.y);
            for (int j = i + 1 + lane; j < n; j += 32) {
                u64 kj = row[j];
                if (kj & SUPBIT) continue;
                float4 bj = sb[j];
                float ih = fmaxf(fminf(bi.z, bj.z) - fmaxf(bi.x, bj.x), 0.0f);
                float iw = fmaxf(fminf(bi.w, bj.w) - fmaxf(bi.y, bj.y), 0.0f);
                float inter = ih * iw;
                float areaj = (bj.z - bj.x) * (bj.w - bj.y);
                float uni = areai + areaj - inter;
                if (inter / (uni + 1e-8f) > 0.3f) row[j] = kj | SUPBIT;
            }
            __syncwarp();
        }
    }

    // ---- compact kept (order preserved) + write out ----
    int kn = 0;
    for (int t0 = 0; t0 < n; t0 += 32) {
        int t = t0 + lane;
        u64 k = (t < n) ? row[t] : SUPBIT;
        bool live = (t < n) && !(k & SUPBIT);
        unsigned ball = __ballot_sync(0xffffffffu, live);
        if (live) g_kept[b][c - 1][kn + __popc(ball & lmask)] = ((u64)c << 43) | k;
        kn += __popc(ball);
    }
    if (lane == 0) g_kcnt[b][c - 1] = kn;
}

// ============================= Kernel 3: select + emit =======================
__global__ __launch_bounds__(1024)
void select_kernel(float* __restrict__ out) {
    __shared__ u64 arr[ARR];
    __shared__ u64 sel[MAXDET];
    __shared__ int Kc;
    const int b = blockIdx.x;
    const int tid = threadIdx.x;
    const int lane = tid & 31;
    const int warp = tid >> 5;

    if (tid == 0) Kc = 0;
    if (tid < MAXDET) sel[tid] = KMAX;
    __syncthreads();

    // gather kept keys from all classes
    for (int c = warp; c < NCLS1; c += 32) {
        int n = g_kcnt[b][c];
        if (n > CAP) n = CAP;
        int base = 0;
        if (lane == 0) base = atomicAdd(&Kc, n);
        base = __shfl_sync(0xffffffffu, base, 0);
        for (int i = lane; i < n; i += 32) {
            int p = base + i;
            if (p < ARR) arr[p] = g_kept[b][c][i];
        }
    }
    __syncthreads();
    int K = Kc;
    if (K > ARR) K = ARR;

    // rank selection: position = #(smaller masked keys); keys unique
    for (int e = tid; e < K; e += 1024) {
        u64 ke = arr[e] & SENT43;
        int rank = 0;
        for (int j = 0; j < K; ++j)
            rank += ((arr[j] & SENT43) < ke) ? 1 : 0;
        if (rank < MAXDET) sel[rank] = arr[e];
    }
    __syncthreads();

    // emit 100 x 6
    float* ob = out + (size_t)b * MAXDET * 6;
    for (int t = tid; t < MAXDET * 6; t += 1024) {
        int row = t / 6;
        int col = t - row * 6;
        u64 sv = sel[row];
        float val = 0.0f;
        if (sv != KMAX) {
            int idx = (int)(sv & 0x7FFu);
            if (col < 4) {
                float4 bx = g_box[b][idx];
                val = (col == 0) ? bx.x : (col == 1) ? bx.y : (col == 2) ? bx.z : bx.w;
            } else if (col == 4) {
                val = (float)((int)(sv >> 43));
            } else {
                unsigned int desc = (unsigned int)((sv >> 11) & 0xFFFFFFFFull);
                val = ord2f(~desc);
            }
        }
        ob[t] = val;
    }
}

extern "C" void kernel_launch(void* const* d_in, const int* in_sizes, int n_in,
                              void* d_out, int out_size) {
    const float* rois   = (const float*)d_in[0];
    const float* probs  = (const float*)d_in[1];
    const float* deltas = (const float*)d_in[2];
    const float* meta   = (const float*)d_in[3];
    float* out = (float*)d_out;

    refine_kernel<<<BATCH * (NROI / ROIS_PER_BLK), ROIS_PER_BLK * 32>>>(rois, probs, deltas, meta);
    class_nms_kernel<<<BATCH * NCLS1 / 4, 128>>>();
    select_kernel<<<BATCH, 1024>>>(out);
}

// round 6
// speedup vs baseline: 1.6041x; 1.3282x over previous
#include <cuda_runtime.h>
#include <cstdint>

#define BATCH 8
#define NROI 2000
#define NCLS 81
#define NCLS1 (NCLS - 1)
#define MAXDET 100
#define META_W (12 + NCLS)
#define CAP 128
#define ARR 2048
#define ROIS_PER_BLK 8

typedef unsigned long long u64;
#define KMAX 0xFFFFFFFFFFFFFFFFull
#define SENT43 ((1ull << 43) - 1)     // sentinel for 43-bit masked keys
#define SUPBIT (1ull << 63)

// ---------------- device scratch -------------------------------------------
__device__ float4 g_box[BATCH][NROI];
__device__ u64    g_lists[BATCH][NCLS1][CAP];  // per-class candidate keys (unordered)
__device__ int    g_cnt[BATCH][NCLS1];
__device__ u64    g_kept[BATCH][NCLS1][CAP];   // per-class kept, sorted; sk format
__device__ int    g_kcnt[BATCH][NCLS1];

__device__ __forceinline__ unsigned int f2ord(float s) {
    unsigned int u = __float_as_uint(s);
    return (u & 0x80000000u) ? ~u : (u | 0x80000000u);
}
__device__ __forceinline__ float ord2f(unsigned int o) {
    unsigned int u = (o & 0x80000000u) ? (o ^ 0x80000000u) : ~o;
    return __uint_as_float(u);
}

// ============================= Kernel 0: zero counters =======================
__global__ void zero_kernel() {
    int t = threadIdx.x;
    if (t < BATCH * NCLS1) ((int*)g_cnt)[t] = 0;
}

// ============================= Kernel 1: refine + bucket =====================
// One warp per ROI: argmax over 81 classes, refine, clip, bucket by class.
__global__ __launch_bounds__(ROIS_PER_BLK * 32)
void refine_kernel(const float* __restrict__ rois,
                   const float* __restrict__ probs,
                   const float* __restrict__ deltas,
                   const float* __restrict__ meta) {
    const int blk  = blockIdx.x;
    const int b    = blk / (NROI / ROIS_PER_BLK);
    const int rblk = blk % (NROI / ROIS_PER_BLK);
    const int warp = threadIdx.x >> 5;
    const int lane = threadIdx.x & 31;
    const int r    = rblk * ROIS_PER_BLK + warp;

    const float* p = probs + ((size_t)b * NROI + r) * NCLS;
    float v = p[lane];
    int ci = lane;
    {
        float v2 = p[lane + 32];
        if (v2 > v) { v = v2; ci = lane + 32; }
        if (lane + 64 < NCLS) {
            float v3 = p[lane + 64];
            if (v3 > v) { v = v3; ci = lane + 64; }
        }
    }
#pragma unroll
    for (int off = 16; off; off >>= 1) {
        float ov = __shfl_down_sync(0xffffffffu, v, off);
        int   oi = __shfl_down_sync(0xffffffffu, ci, off);
        if (ov > v || (ov == v && oi < ci)) { v = ov; ci = oi; }
    }
    if (lane == 0) {
        float h = meta[4], w = meta[5];
        float sy = h - 1.0f, sx = w - 1.0f;
        const float* mw = meta + (size_t)b * META_W + 7;
        float wy1 = mw[0] / sy;
        float wx1 = mw[1] / sx;
        float wy2 = (mw[2] - 1.0f) / sy;
        float wx2 = (mw[3] - 1.0f) / sx;

        float4 roi = *reinterpret_cast<const float4*>(rois + ((size_t)b * NROI + r) * 4);
        float4 d   = *reinterpret_cast<const float4*>(deltas + (((size_t)b * NROI + r) * NCLS + ci) * 4);
        d.x *= 0.1f; d.y *= 0.1f; d.z *= 0.2f; d.w *= 0.2f;
        float hh = roi.z - roi.x;
        float ww = roi.w - roi.y;
        float cy = roi.x + 0.5f * hh + d.x * hh;
        float cx = roi.y + 0.5f * ww + d.y * ww;
        hh *= expf(d.z);
        ww *= expf(d.w);
        float y1 = cy - 0.5f * hh;
        float x1 = cx - 0.5f * ww;
        float y2 = y1 + hh;
        float x2 = x1 + ww;
        y1 = fminf(fmaxf(y1, wy1), wy2);
        x1 = fminf(fmaxf(x1, wx1), wx2);
        y2 = fminf(fmaxf(y2, wy1), wy2);
        x2 = fminf(fmaxf(x2, wx1), wx2);

        g_box[b][r] = make_float4(y1, x1, y2, x2);
        if ((ci > 0) && (v >= 0.7f)) {
            unsigned int desc = ~f2ord(v);
            u64 k = (((u64)desc) << 11) | (unsigned int)r;   // masked43
            int pos = atomicAdd(&g_cnt[b][ci - 1], 1);
            if (pos < CAP) g_lists[b][ci - 1][pos] = k;
        }
    }
}

// ============================= Kernel 2: per-class NMS =======================
// One warp per (batch, class): load list, warp-sort, greedy NMS, write kept.
__global__ __launch_bounds__(128)
void class_nms_kernel() {
    __shared__ u64    lists[4][CAP];
    __shared__ float4 sbox[4][CAP];
    const int wib  = threadIdx.x >> 5;
    const int lane = threadIdx.x & 31;
    const int g    = blockIdx.x * 4 + wib;
    const int b    = g / NCLS1;
    const int c    = g % NCLS1;                 // 0-based; class id = c+1
    u64* row = lists[wib];
    float4* sb = sbox[wib];
    const unsigned lmask = (1u << lane) - 1u;

    int n = g_cnt[b][c];
    if (n > CAP) n = CAP;
    for (int i = lane; i < n; i += 32) row[i] = g_lists[b][c][i];
    __syncwarp();

    if (n > 1) {
        int P = 2;
        while (P < n) P <<= 1;
        for (int t = n + lane; t < P; t += 32) row[t] = SENT43;
        __syncwarp();
        // warp bitonic: ascending masked key = (score desc, idx asc)
        for (int k2 = 2; k2 <= P; k2 <<= 1) {
            for (int j = k2 >> 1; j > 0; j >>= 1) {
                for (int i0 = 0; i0 < P; i0 += 32) {
                    int i = i0 + lane;
                    int ixj = i ^ j;
                    if (i < P && ixj > i && ixj < P) {
                        u64 a = row[i];
                        u64 bb = row[ixj];
                        bool up = ((i & k2) == 0);
                        if ((a > bb) == up) { row[i] = bb; row[ixj] = a; }
                    }
                }
                __syncwarp();
            }
        }
        // stage boxes
        for (int i = lane; i < n; i += 32)
            sb[i] = g_box[b][(int)(row[i] & 0x7FFu)];
        __syncwarp();
        // greedy NMS
        for (int i = 0; i < n; ++i) {
            u64 ki = row[i];
            if (ki & SUPBIT) continue;
            float4 bi = sb[i];
            float areai = (bi.z - bi.x) * (bi.w - bi.y);
            for (int j = i + 1 + lane; j < n; j += 32) {
                u64 kj = row[j];
                if (kj & SUPBIT) continue;
                float4 bj = sb[j];
                float ih = fmaxf(fminf(bi.z, bj.z) - fmaxf(bi.x, bj.x), 0.0f);
                float iw = fmaxf(fminf(bi.w, bj.w) - fmaxf(bi.y, bj.y), 0.0f);
                float inter = ih * iw;
                float areaj = (bj.z - bj.x) * (bj.w - bj.y);
                float uni = areai + areaj - inter;
                if (inter / (uni + 1e-8f) > 0.3f) row[j] = kj | SUPBIT;
            }
            __syncwarp();
        }
    }

    // compact kept (order preserved): sk = (masked43 << 7) | classid
    int kn = 0;
    for (int t0 = 0; t0 < n; t0 += 32) {
        int t = t0 + lane;
        u64 k = (t < n) ? row[t] : SUPBIT;
        bool live = (t < n) && !(k & SUPBIT);
        unsigned ball = __ballot_sync(0xffffffffu, live);
        if (live) g_kept[b][c][kn + __popc(ball & lmask)] = (k << 7) | (unsigned)(c + 1);
        kn += __popc(ball);
    }
    if (lane == 0) g_kcnt[b][c] = kn;
}

// ============================= Kernel 3: select + emit =======================
__global__ __launch_bounds__(1024)
void select_kernel(float* __restrict__ out) {
    __shared__ u64 arr[ARR];
    __shared__ int Kc;
    const int b = blockIdx.x;
    const int tid = threadIdx.x;
    const int lane = tid & 31;
    const int warp = tid >> 5;

    if (tid == 0) Kc = 0;
    __syncthreads();

    // gather kept keys from all classes (sk already encodes class)
    for (int c = warp; c < NCLS1; c += 32) {
        int n = g_kcnt[b][c];
        if (n > CAP) n = CAP;
        int base = 0;
        if (lane == 0) base = atomicAdd(&Kc, n);
        base = __shfl_sync(0xffffffffu, base, 0);
        for (int i = lane; i < n; i += 32) {
            int p = base + i;
            if (p < ARR) arr[p] = g_kept[b][c][i];
        }
    }
    __syncthreads();
    int K = Kc;
    if (K > ARR) K = ARR;
    int P = 128;
    while (P < K) P <<= 1;
    for (int t = K + tid; t < P; t += 1024) arr[t] = KMAX;
    __syncthreads();

    // block bitonic sort ascending: (score desc, idx asc) first
    for (int k2 = 2; k2 <= P; k2 <<= 1) {
        for (int j = k2 >> 1; j > 0; j >>= 1) {
            for (int i0 = 0; i0 < P; i0 += 1024) {
                int i = i0 + tid;
                int ixj = i ^ j;
                if (i < P && ixj > i && ixj < P) {
                    u64 a = arr[i];
                    u64 bb = arr[ixj];
                    bool up = ((i & k2) == 0);
                    if ((a > bb) == up) { arr[i] = bb; arr[ixj] = a; }
                }
            }
            __syncthreads();
        }
    }

    // emit 100 x 6
    float* ob = out + (size_t)b * MAXDET * 6;
    for (int t = tid; t < MAXDET * 6; t += 1024) {
        int row = t / 6;
        int col = t - row * 6;
        u64 sv = arr[row];
        float val = 0.0f;
        if (sv != KMAX) {
            int idx = (int)((sv >> 7) & 0x7FFu);
            if (col < 4) {
                float4 bx = g_box[b][idx];
                val = (col == 0) ? bx.x : (col == 1) ? bx.y : (col == 2) ? bx.z : bx.w;
            } else if (col == 4) {
                val = (float)((int)(sv & 0x7Fu));
            } else {
                unsigned int desc = (unsigned int)((sv >> 18) & 0xFFFFFFFFull);
                val = ord2f(~desc);
            }
        }
        ob[t] = val;
    }
}

extern "C" void kernel_launch(void* const* d_in, const int* in_sizes, int n_in,
                              void* d_out, int out_size) {
    const float* rois   = (const float*)d_in[0];
    const float* probs  = (const float*)d_in[1];
    const float* deltas = (const float*)d_in[2];
    const float* meta   = (const float*)d_in[3];
    float* out = (float*)d_out;

    zero_kernel<<<1, BATCH * NCLS1>>>();
    refine_kernel<<<BATCH * (NROI / ROIS_PER_BLK), ROIS_PER_BLK * 32>>>(rois, probs, deltas, meta);
    class_nms_kernel<<<BATCH * NCLS1 / 4, 128>>>();
    select_kernel<<<BATCH, 1024>>>(out);
}

// round 7
// speedup vs baseline: 1.9024x; 1.1860x over previous
#include <cuda_runtime.h>
#include <cstdint>

#define BATCH 8
#define NROI 2000
#define NCLS 81
#define NCLS1 (NCLS - 1)
#define MAXDET 100
#define META_W (12 + NCLS)
#define CAP 128
#define ARR 2048
#define ROIS_PER_BLK 8

typedef unsigned long long u64;
#define KMAX 0xFFFFFFFFFFFFFFFFull
#define SENT43 ((1ull << 43) - 1)
#define SUPBIT (1ull << 63)

// ---------------- device scratch -------------------------------------------
__device__ float4 g_box[BATCH][NROI];
__device__ u64    g_lists[BATCH][NCLS1][CAP];
__device__ int    g_cnt[BATCH][NCLS1];
__device__ u64    g_kept[BATCH][NCLS1][CAP];
__device__ int    g_kcnt[BATCH][NCLS1];

__device__ __forceinline__ unsigned int f2ord(float s) {
    unsigned int u = __float_as_uint(s);
    return (u & 0x80000000u) ? ~u : (u | 0x80000000u);
}
__device__ __forceinline__ float ord2f(unsigned int o) {
    unsigned int u = (o & 0x80000000u) ? (o ^ 0x80000000u) : ~o;
    return __uint_as_float(u);
}

// ============================= Kernel 0: zero counters =======================
__global__ void zero_kernel() {
    int t = threadIdx.x;
    if (t < BATCH * NCLS1) ((int*)g_cnt)[t] = 0;
}

// ============================= Kernel 1: refine + bucket =====================
__global__ __launch_bounds__(ROIS_PER_BLK * 32)
void refine_kernel(const float* __restrict__ rois,
                   const float* __restrict__ probs,
                   const float* __restrict__ deltas,
                   const float* __restrict__ meta) {
    const int blk  = blockIdx.x;
    const int b    = blk / (NROI / ROIS_PER_BLK);
    const int rblk = blk % (NROI / ROIS_PER_BLK);
    const int warp = threadIdx.x >> 5;
    const int lane = threadIdx.x & 31;
    const int r    = rblk * ROIS_PER_BLK + warp;

    const float* p = probs + ((size_t)b * NROI + r) * NCLS;
    float v = p[lane];
    int ci = lane;
    {
        float v2 = p[lane + 32];
        if (v2 > v) { v = v2; ci = lane + 32; }
        if (lane + 64 < NCLS) {
            float v3 = p[lane + 64];
            if (v3 > v) { v = v3; ci = lane + 64; }
        }
    }
#pragma unroll
    for (int off = 16; off; off >>= 1) {
        float ov = __shfl_down_sync(0xffffffffu, v, off);
        int   oi = __shfl_down_sync(0xffffffffu, ci, off);
        if (ov > v || (ov == v && oi < ci)) { v = ov; ci = oi; }
    }
    if (lane == 0) {
        float h = meta[4], w = meta[5];
        float sy = h - 1.0f, sx = w - 1.0f;
        const float* mw = meta + (size_t)b * META_W + 7;
        float wy1 = mw[0] / sy;
        float wx1 = mw[1] / sx;
        float wy2 = (mw[2] - 1.0f) / sy;
        float wx2 = (mw[3] - 1.0f) / sx;

        float4 roi = *reinterpret_cast<const float4*>(rois + ((size_t)b * NROI + r) * 4);
        float4 d   = *reinterpret_cast<const float4*>(deltas + (((size_t)b * NROI + r) * NCLS + ci) * 4);
        d.x *= 0.1f; d.y *= 0.1f; d.z *= 0.2f; d.w *= 0.2f;
        float hh = roi.z - roi.x;
        float ww = roi.w - roi.y;
        float cy = roi.x + 0.5f * hh + d.x * hh;
        float cx = roi.y + 0.5f * ww + d.y * ww;
        hh *= expf(d.z);
        ww *= expf(d.w);
        float y1 = cy - 0.5f * hh;
        float x1 = cx - 0.5f * ww;
        float y2 = y1 + hh;
        float x2 = x1 + ww;
        y1 = fminf(fmaxf(y1, wy1), wy2);
        x1 = fminf(fmaxf(x1, wx1), wx2);
        y2 = fminf(fmaxf(y2, wy1), wy2);
        x2 = fminf(fmaxf(x2, wx1), wx2);

        g_box[b][r] = make_float4(y1, x1, y2, x2);
        if ((ci > 0) && (v >= 0.7f)) {
            unsigned int desc = ~f2ord(v);
            u64 k = (((u64)desc) << 11) | (unsigned int)r;
            int pos = atomicAdd(&g_cnt[b][ci - 1], 1);
            if (pos < CAP) g_lists[b][ci - 1][pos] = k;
        }
    }
}

// ============================= Kernel 2: per-class NMS =======================
__global__ __launch_bounds__(128)
void class_nms_kernel() {
    __shared__ u64    lists[4][CAP];
    __shared__ float4 sbox[4][CAP];
    const int wib  = threadIdx.x >> 5;
    const int lane = threadIdx.x & 31;
    const int g    = blockIdx.x * 4 + wib;
    const int b    = g / NCLS1;
    const int c    = g % NCLS1;
    u64* row = lists[wib];
    float4* sb = sbox[wib];
    const unsigned lmask = (1u << lane) - 1u;

    int n = g_cnt[b][c];
    if (n > CAP) n = CAP;
    for (int i = lane; i < n; i += 32) row[i] = g_lists[b][c][i];
    __syncwarp();

    if (n > 1) {
        int P = 2;
        while (P < n) P <<= 1;
        for (int t = n + lane; t < P; t += 32) row[t] = SENT43;
        __syncwarp();
        for (int k2 = 2; k2 <= P; k2 <<= 1) {
            for (int j = k2 >> 1; j > 0; j >>= 1) {
                for (int i0 = 0; i0 < P; i0 += 32) {
                    int i = i0 + lane;
                    int ixj = i ^ j;
                    if (i < P && ixj > i && ixj < P) {
                        u64 a = row[i];
                        u64 bb = row[ixj];
                        bool up = ((i & k2) == 0);
                        if ((a > bb) == up) { row[i] = bb; row[ixj] = a; }
                    }
                }
                __syncwarp();
            }
        }
        for (int i = lane; i < n; i += 32)
            sb[i] = g_box[b][(int)(row[i] & 0x7FFu)];
        __syncwarp();
        for (int i = 0; i < n; ++i) {
            u64 ki = row[i];
            if (ki & SUPBIT) continue;
            float4 bi = sb[i];
            float areai = (bi.z - bi.x) * (bi.w - bi.y);
            for (int j = i + 1 + lane; j < n; j += 32) {
                u64 kj = row[j];
                if (kj & SUPBIT) continue;
                float4 bj = sb[j];
                float ih = fmaxf(fminf(bi.z, bj.z) - fmaxf(bi.x, bj.x), 0.0f);
                float iw = fmaxf(fminf(bi.w, bj.w) - fmaxf(bi.y, bj.y), 0.0f);
                float inter = ih * iw;
                float areaj = (bj.z - bj.x) * (bj.w - bj.y);
                float uni = areai + areaj - inter;
                if (inter / (uni + 1e-8f) > 0.3f) row[j] = kj | SUPBIT;
            }
            __syncwarp();
        }
    }

    int kn = 0;
    for (int t0 = 0; t0 < n; t0 += 32) {
        int t = t0 + lane;
        u64 k = (t < n) ? row[t] : SUPBIT;
        bool live = (t < n) && !(k & SUPBIT);
        unsigned ball = __ballot_sync(0xffffffffu, live);
        if (live) g_kept[b][c][kn + __popc(ball & lmask)] = (k << 7) | (unsigned)(c + 1);
        kn += __popc(ball);
    }
    if (lane == 0) g_kcnt[b][c] = kn;
}

// ============================= Kernel 3: radix-select + emit =================
// sk = masked43<<7 | cls. desc(score) occupies sk bits [49:18].
__global__ __launch_bounds__(1024)
void select_kernel(float* __restrict__ out) {
    __shared__ u64 arr[ARR];                 // kept keys
    __shared__ u64 Lk[ARR];                  // finalist keys
    __shared__ unsigned short candA[ARR];
    __shared__ unsigned short candB[ARR];
    __shared__ unsigned short acc[ARR];
    __shared__ int bins[256];
    __shared__ u64 sel[MAXDET];
    __shared__ int Kc, naccS, ncandNextS, tbinS, doneS;

    const int b = blockIdx.x;
    const int tid = threadIdx.x;
    const int lane = tid & 31;
    const int warp = tid >> 5;

    if (tid == 0) { Kc = 0; naccS = 0; doneS = 0; }
    if (tid < MAXDET) sel[tid] = KMAX;
    __syncthreads();

    // ---- gather kept keys ----
    for (int c = warp; c < NCLS1; c += 32) {
        int n = g_kcnt[b][c];
        if (n > CAP) n = CAP;
        int base = 0;
        if (lane == 0) base = atomicAdd(&Kc, n);
        base = __shfl_sync(0xffffffffu, base, 0);
        for (int i = lane; i < n; i += 32) {
            int p = base + i;
            if (p < ARR) arr[p] = g_kept[b][c][i];
        }
    }
    __syncthreads();
    int K = Kc;
    if (K > ARR) K = ARR;

    int ncand;
    if (K <= MAXDET) {
        // everyone is a finalist
        for (int t = tid; t < K; t += 1024) acc[t] = (unsigned short)t;
        if (tid == 0) naccS = K;
        ncand = 0;
        __syncthreads();
    } else {
        for (int t = tid; t < K; t += 1024) candA[t] = (unsigned short)t;
        ncand = K;
        __syncthreads();

        const int shifts[3] = {42, 34, 26};
#pragma unroll
        for (int rnd = 0; rnd < 3; ++rnd) {
            if (doneS) break;
            int shift = shifts[rnd];
            // zero bins
            if (tid < 256) bins[tid] = 0;
            if (tid == 0) ncandNextS = 0;
            __syncthreads();
            // histogram candidates
            for (int i = tid; i < ncand; i += 1024) {
                int bin = (int)((arr[candA[i]] >> shift) & 0xFF);
                atomicAdd(&bins[bin], 1);
            }
            __syncthreads();
            // warp 0: prefix over 256 bins, find threshold bin t
            if (warp == 0) {
                int need = MAXDET - naccS;
                int carry = 0;
                int tbin = 255;
                bool found = false;
#pragma unroll
                for (int ch = 0; ch < 8; ++ch) {
                    int v = bins[ch * 32 + lane];
                    int incl = v;
#pragma unroll
                    for (int o = 1; o < 32; o <<= 1) {
                        int x = __shfl_up_sync(0xffffffffu, incl, o);
                        if (lane >= o) incl += x;
                    }
                    int cum = carry + incl;
                    unsigned ball = __ballot_sync(0xffffffffu, cum >= need);
                    if (!found && ball) {
                        tbin = ch * 32 + (__ffs(ball) - 1);
                        found = true;
                    }
                    carry = __shfl_sync(0xffffffffu, carry + incl, 31);
                }
                if (lane == 0) tbinS = tbin;
            }
            __syncthreads();
            int tbin = tbinS;
            // partition: bin<t -> accepted, bin==t -> next candidates
            for (int i = tid; i < ncand; i += 1024) {
                unsigned short idx = candA[i];
                int bin = (int)((arr[idx] >> shift) & 0xFF);
                if (bin < tbin) {
                    acc[atomicAdd(&naccS, 1)] = idx;
                } else if (bin == tbin) {
                    candB[atomicAdd(&ncandNextS, 1)] = idx;
                }
            }
            __syncthreads();
            ncand = ncandNextS;
            // copy candB->candA
            for (int i = tid; i < ncand; i += 1024) candA[i] = candB[i];
            if (tid == 0 && naccS + ncand <= MAXDET) doneS = 1;
            __syncthreads();
        }
    }

    // ---- finalists L = acc ∪ candA; rank-select exact top-100 ----
    int nacc = naccS;
    int nL = nacc + ncand;
    if (nL > ARR) nL = ARR;
    for (int t = tid; t < nL; t += 1024)
        Lk[t] = arr[(t < nacc) ? acc[t] : candA[t - nacc]];
    __syncthreads();

    for (int e = tid; e < nL; e += 1024) {
        u64 ke = Lk[e];
        int rank = 0;
        for (int j = 0; j < nL; ++j)
            rank += (Lk[j] < ke) ? 1 : 0;
        if (rank < MAXDET) sel[rank] = ke;
    }
    __syncthreads();

    // ---- emit 100 x 6 ----
    float* ob = out + (size_t)b * MAXDET * 6;
    for (int t = tid; t < MAXDET * 6; t += 1024) {
        int row = t / 6;
        int col = t - row * 6;
        u64 sv = sel[row];
        float val = 0.0f;
        if (sv != KMAX) {
            int idx = (int)((sv >> 7) & 0x7FFu);
            if (col < 4) {
                float4 bx = g_box[b][idx];
                val = (col == 0) ? bx.x : (col == 1) ? bx.y : (col == 2) ? bx.z : bx.w;
            } else if (col == 4) {
                val = (float)((int)(sv & 0x7Fu));
            } else {
                unsigned int desc = (unsigned int)((sv >> 18) & 0xFFFFFFFFull);
                val = ord2f(~desc);
            }
        }
        ob[t] = val;
    }
}

extern "C" void kernel_launch(void* const* d_in, const int* in_sizes, int n_in,
                              void* d_out, int out_size) {
    const float* rois   = (const float*)d_in[0];
    const float* probs  = (const float*)d_in[1];
    const float* deltas = (const float*)d_in[2];
    const float* meta   = (const float*)d_in[3];
    float* out = (float*)d_out;

    zero_kernel<<<1, BATCH * NCLS1>>>();
    refine_kernel<<<BATCH * (NROI / ROIS_PER_BLK), ROIS_PER_BLK * 32>>>(rois, probs, deltas, meta);
    class_nms_kernel<<<BATCH * NCLS1 / 4, 128>>>();
    select_kernel<<<BATCH, 1024>>>(out);
}